// round 14
// baseline (speedup 1.0000x reference)
#include <cuda_runtime.h>
#include <cuda_fp16.h>
#include <math.h>
#include <stdint.h>

#define T_TOKENS 8192
#define H_DIM    2048
#define I_DIM    1408
#define N_EXP    8
#define MAXTOK   8192
#define TOTROWS  (2*T_TOKENS)
#define WELEMS   (N_EXP * I_DIM * H_DIM)
#define SPLIT_N4 (WELEMS / 4)
#define SPLIT_IT 4
#define SPLIT_BLK ((SPLIT_N4 + 256*SPLIT_IT - 1) / (256*SPLIT_IT))
#define RTOK 8
#define RBLOCKS (T_TOKENS / RTOK)          // 1024
#define PREP_SMEM (N_EXP * H_DIM * 4)      // 65536 B (router rw cache)

// ---------------- scratch (static device globals) ----------------
__device__ __half g_xn[(size_t)T_TOKENS*H_DIM];
__device__ __half g_h [(size_t)(TOTROWS+128)*I_DIM];
__device__ int    g_cnt[N_EXP];
__device__ int    g_off[N_EXP];
__device__ int    g_tok[N_EXP*MAXTOK];
__device__ float  g_wt [N_EXP*MAXTOK];
// fp16 weights (single term)
__device__ __half g_wg[(size_t)WELEMS];
__device__ __half g_wu[(size_t)WELEMS];
__device__ __half g_wd[(size_t)WELEMS];

// ---------------- helpers ----------------
__device__ __forceinline__ uint32_t smem_u32(const void* p) {
    uint32_t a;
    asm("{ .reg .u64 t; cvta.to.shared.u64 t, %1; cvt.u32.u64 %0, t; }" : "=r"(a) : "l"(p));
    return a;
}
__device__ __forceinline__ void ldsm_x4(uint32_t* r, uint32_t addr) {
    asm volatile("ldmatrix.sync.aligned.m8n8.x4.shared.b16 {%0,%1,%2,%3}, [%4];"
        : "=r"(r[0]), "=r"(r[1]), "=r"(r[2]), "=r"(r[3]) : "r"(addr));
}
__device__ __forceinline__ void mma_fp16(float* c, const uint32_t* a, const uint32_t* b) {
    asm volatile(
        "mma.sync.aligned.m16n8k16.row.col.f32.f16.f16.f32 "
        "{%0,%1,%2,%3}, {%4,%5,%6,%7}, {%8,%9}, {%0,%1,%2,%3};"
        : "+f"(c[0]), "+f"(c[1]), "+f"(c[2]), "+f"(c[3])
        : "r"(a[0]), "r"(a[1]), "r"(a[2]), "r"(a[3]), "r"(b[0]), "r"(b[1]));
}
__device__ __forceinline__ void cp16(uint32_t dst, const void* src, uint32_t sz) {
    asm volatile("cp.async.cg.shared.global [%0], [%1], 16, %2;"
        :: "r"(dst), "l"(src), "r"(sz) : "memory");
}
#define CP_COMMIT() asm volatile("cp.async.commit_group;" ::: "memory")
template<int N> __device__ __forceinline__ void cp_wait() {
    asm volatile("cp.async.wait_group %0;" :: "n"(N) : "memory");
}
__device__ __forceinline__ uint32_t packh2(__half a, __half b) {
    __half2 v = __halves2half2(a, b);
    return *reinterpret_cast<uint32_t*>(&v);
}
__device__ __forceinline__ float warp_sum(float v) {
#pragma unroll
    for (int o = 16; o > 0; o >>= 1)
        v += __shfl_xor_sync(0xFFFFFFFFu, v, o);
    return v;
}

// ---------------------------------------------------------------------------
__global__ void reset_kernel() {
    if (threadIdx.x < N_EXP) g_cnt[threadIdx.x] = 0;
}

// ---------------------------------------------------------------------------
// Fused prep kernel:
//   blocks [0, RBLOCKS)        -> router, 8 tokens/block, rw cached in smem
//   blocks [RBLOCKS, +3*SPLIT_BLK) -> weight cast fp32 -> fp16, 4 chunks/thread
__global__ __launch_bounds__(256) void prep_kernel(
    const float* __restrict__ hs,
    const float* __restrict__ rmsw,
    const float* __restrict__ rw,
    const float* __restrict__ wg,
    const float* __restrict__ wu,
    const float* __restrict__ wd,
    float* __restrict__ out,
    float* __restrict__ out_logits)
{
    const int tid = threadIdx.x;

    if (blockIdx.x >= RBLOCKS) {
        // ---------------- weight cast part ----------------
        int sb = blockIdx.x - RBLOCKS;
        int w = sb / SPLIT_BLK;
        const float* src = (w == 0) ? wg : (w == 1) ? wu : wd;
        __half* hi = (w == 0) ? g_wg : (w == 1) ? g_wu : g_wd;
        int base = (sb - w * SPLIT_BLK) * 256 * SPLIT_IT + tid;
#pragma unroll
        for (int it = 0; it < SPLIT_IT; it++, base += 256) {
            if (base < SPLIT_N4) {
                float4 v = ((const float4*)src)[base];
                ((uint2*)hi)[base] = make_uint2(
                    packh2(__float2half_rn(v.x), __float2half_rn(v.y)),
                    packh2(__float2half_rn(v.z), __float2half_rn(v.w)));
            }
        }
        return;
    }

    // ---------------- router part: 8 tokens per block ----------------
    extern __shared__ float s_rw[];    // [N_EXP * H_DIM] fp32, 64 KB
    const int wid  = tid >> 5;
    const int lane = tid & 31;

    // cache router weights once
    {
        const float4* rw4 = (const float4*)rw;
        float4* s4 = (float4*)s_rw;
#pragma unroll
        for (int i = 0; i < (N_EXP * H_DIM / 4) / 256; i++)
            s4[tid + i * 256] = rw4[tid + i * 256];
    }

    __shared__ float swred[8];
    __shared__ float sacc[8][N_EXP];
    __shared__ float s_scale;
    __shared__ float slog[N_EXP];
    __syncthreads();

    for (int tk = 0; tk < RTOK; tk++) {
        const int t = blockIdx.x * RTOK + tk;
        const float4* x4 = (const float4*)(hs + (size_t)t * H_DIM);
        const float4* rm4 = (const float4*)rmsw;

        // zero this token's output row (gemm2 accumulates atomically)
        {
            float4 z = make_float4(0.f, 0.f, 0.f, 0.f);
            float4* o4 = (float4*)(out + (size_t)t * H_DIM);
#pragma unroll
            for (int it = 0; it < 2; it++) o4[tid + it * 256] = z;
        }

        // sum of squares
        float ss = 0.f;
#pragma unroll
        for (int it = 0; it < 2; it++) {
            float4 v = x4[tid + it * 256];
            ss += v.x*v.x + v.y*v.y + v.z*v.z + v.w*v.w;
        }
        ss = warp_sum(ss);
        if (lane == 0) swred[wid] = ss;
        __syncthreads();
        if (tid == 0) {
            float tot = 0.f;
#pragma unroll
            for (int w = 0; w < 8; w++) tot += swred[w];
            s_scale = rsqrtf(tot / (float)H_DIM + 1e-6f);
        }
        __syncthreads();
        const float scale = s_scale;

        // normalize (store fp16) + 8 router dots from smem
        float acc[N_EXP];
#pragma unroll
        for (int e = 0; e < N_EXP; e++) acc[e] = 0.f;
#pragma unroll
        for (int it = 0; it < 2; it++) {
            int i4 = tid + it * 256;
            float4 xv = x4[i4];
            float4 wv = rm4[i4];
            xv.x *= scale * wv.x;  xv.y *= scale * wv.y;
            xv.z *= scale * wv.z;  xv.w *= scale * wv.w;
            *(uint2*)(g_xn + (size_t)t * H_DIM + i4 * 4) = make_uint2(
                packh2(__float2half_rn(xv.x), __float2half_rn(xv.y)),
                packh2(__float2half_rn(xv.z), __float2half_rn(xv.w)));
#pragma unroll
            for (int e = 0; e < N_EXP; e++) {
                float4 rv = ((const float4*)s_rw)[e * (H_DIM/4) + i4];
                acc[e] += xv.x*rv.x + xv.y*rv.y + xv.z*rv.z + xv.w*rv.w;
            }
        }
#pragma unroll
        for (int e = 0; e < N_EXP; e++) {
            float v = warp_sum(acc[e]);
            if (lane == 0) sacc[wid][e] = v;
        }
        __syncthreads();
        if (tid < N_EXP) {
            float tot = 0.f;
#pragma unroll
            for (int w = 0; w < 8; w++) tot += sacc[w][tid];
            slog[tid] = tot;
        }
        __syncthreads();

        if (tid == 0) {
            float l[N_EXP], m = -1e30f;
#pragma unroll
            for (int e = 0; e < N_EXP; e++) {
                l[e] = slog[e];
                out_logits[(size_t)t * N_EXP + e] = l[e];
                m = fmaxf(m, l[e]);
            }
            float p[N_EXP], s = 0.f;
#pragma unroll
            for (int e = 0; e < N_EXP; e++) { p[e] = expf(l[e] - m); s += p[e]; }
#pragma unroll
            for (int e = 0; e < N_EXP; e++) p[e] /= s;

            int a = 0;
#pragma unroll
            for (int e = 1; e < N_EXP; e++) if (p[e] > p[a]) a = e;
            int b = (a == 0) ? 1 : 0;
#pragma unroll
            for (int e = 0; e < N_EXP; e++) if (e != a && p[e] > p[b]) b = e;

            float wsum = p[a] + p[b] + 1e-20f;
            float wa = p[a] / wsum, wb = p[b] / wsum;

            int pa = atomicAdd(&g_cnt[a], 1);
            g_tok[a * MAXTOK + pa] = t;  g_wt[a * MAXTOK + pa] = wa;
            int pb = atomicAdd(&g_cnt[b], 1);
            g_tok[b * MAXTOK + pb] = t;  g_wt[b * MAXTOK + pb] = wb;
        }
        __syncthreads();   // protect swred/sacc/slog reuse across tokens
    }
}

// ---------------------------------------------------------------------------
__global__ void offsets_kernel() {
    int run = 0;
    for (int e = 0; e < N_EXP; e++) { g_off[e] = run; run += g_cnt[e]; }
}

// ---------------------------------------------------------------------------
// fp16 HMMA GEMMs, 3-stage cp.async pipeline, one sync per K-tile.
// Block tile 128(M) x 64(N), K-tile 64, 256 threads, warp grid 4x2 (warp 32x32),
// 2 CTAs/SM. LDSM addresses fully precomputed in u32.
#define AS 72
#define G1_STG_E (256*AS)                  // halves per stage = 18432
#define G1_STG_B (G1_STG_E*2)              // 36864 B
#define G1_SMEM  (3*G1_STG_B)              // 110592 B
#define G2_STG_E (192*AS)                  // 13824
#define G2_STG_B (G2_STG_E*2)              // 27648 B
#define G2_SMEM  (3*G2_STG_B)              // 82944 B

__global__ __launch_bounds__(256, 2) void gemm1_kernel()
{
    const int e  = blockIdx.z;
    const int mt = blockIdx.y;
    const int nt = blockIdx.x;
    const int cnt = g_cnt[e];
    if (mt * 128 >= cnt) return;
    const int tid = threadIdx.x;
    const int wid = tid >> 5;
    const int lane = tid & 31;

    extern __shared__ __half sm[];
    __shared__ int stok[128];

    if (tid < 128) {
        int row = mt * 128 + tid;
        stok[tid] = (row < cnt) ? g_tok[e * MAXTOK + row] : -1;
    }
    __syncthreads();

    const size_t wbase = (size_t)e * I_DIM * H_DIM + (size_t)(nt * 64) * H_DIM;
    const __half* wgp = g_wg + wbase;
    const __half* wup = g_wu + wbase;

    const uint32_t smb = smem_u32(sm);

    const __half* aSrc[4]; uint32_t aDst[4], aSz[4];
#pragma unroll
    for (int p = 0; p < 4; p++) {
        int q = tid + p * 256;
        int r = q >> 3, c8 = (q & 7) * 8;
        int tok = stok[r];
        aSz[p]  = tok >= 0 ? 16u : 0u;
        aSrc[p] = g_xn + (size_t)(tok < 0 ? 0 : tok) * H_DIM + c8;
        aDst[p] = smb + (uint32_t)(r * AS + c8) * 2u;
    }
    size_t bOfs[2]; uint32_t bDst[2];
#pragma unroll
    for (int p = 0; p < 2; p++) {
        int q = tid + p * 256;
        int n = q >> 3, c8 = (q & 7) * 8;
        bOfs[p] = (size_t)n * H_DIM + c8;
        bDst[p] = smb + (uint32_t)(n * AS + c8) * 2u;
    }

#define G1_LOAD(S, KK) do {                                                     \
    uint32_t so = (uint32_t)(S) * G1_STG_B;                                     \
    _Pragma("unroll")                                                           \
    for (int p = 0; p < 4; p++)                                                 \
        cp16(aDst[p] + so, aSrc[p] + (KK), aSz[p]);                             \
    _Pragma("unroll")                                                           \
    for (int p = 0; p < 2; p++) {                                               \
        size_t o = bOfs[p] + (KK);                                              \
        cp16(bDst[p] + so + 128*AS*2, wgp + o, 16u);                            \
        cp16(bDst[p] + so + 192*AS*2, wup + o, 16u);                            \
    }                                                                           \
} while (0)

    float cg[2][4][4], cu[2][4][4];
#pragma unroll
    for (int i = 0; i < 2; i++)
#pragma unroll
        for (int j = 0; j < 4; j++)
#pragma unroll
            for (int k = 0; k < 4; k++) { cg[i][j][k] = 0.f; cu[i][j][k] = 0.f; }

    const int wm = wid >> 1;
    const int wn = wid & 1;
    const int lr = lane & 15;
    const int lc = (lane >> 4) * 8;

    const uint32_t aB  = smb + (uint32_t)(((wm*32 + lr) * AS + lc) * 2);
    const uint32_t bgB = smb + (uint32_t)((128*AS + (wn*32 + lr) * AS + lc) * 2);
    const uint32_t buB = bgB + 64*AS*2;

    G1_LOAD(0, 0);
    CP_COMMIT();
    G1_LOAD(1, 64);
    CP_COMMIT();

    const int KT = H_DIM / 64;
    int cur = 0, nxt = 2;
#pragma unroll 3
    for (int kt = 0; kt < KT; kt++) {
        if (kt + 1 < KT) cp_wait<1>(); else cp_wait<0>();
        __syncthreads();
        if (kt + 2 < KT) {
            G1_LOAD(nxt, (kt + 2) * 64);
            CP_COMMIT();
        }

        const uint32_t so = (uint32_t)cur * G1_STG_B;

#pragma unroll
        for (int ks = 0; ks < 4; ks++) {
            uint32_t ah[2][4];
#pragma unroll
            for (int mf = 0; mf < 2; mf++)
                ldsm_x4(ah[mf], aB + so + (uint32_t)((mf*16*AS + ks*16) * 2));
            uint32_t bg[2][4], bu[2][4];
#pragma unroll
            for (int n2 = 0; n2 < 2; n2++) {
                uint32_t fo = (uint32_t)((n2*16*AS + ks*16) * 2);
                ldsm_x4(bg[n2], bgB + so + fo);
                ldsm_x4(bu[n2], buB + so + fo);
            }
#pragma unroll
            for (int mf = 0; mf < 2; mf++)
#pragma unroll
            for (int nf = 0; nf < 4; nf++) {
                int n2 = nf >> 1, nh = nf & 1;
                uint32_t bG[2] = { bg[n2][nh], bg[n2][nh+2] };
                uint32_t bU[2] = { bu[n2][nh], bu[n2][nh+2] };
                mma_fp16(cg[mf][nf], ah[mf], bG);
                mma_fp16(cu[mf][nf], ah[mf], bU);
            }
        }
        cur = (cur == 2) ? 0 : cur + 1;
        nxt = (nxt == 2) ? 0 : nxt + 1;
    }
#undef G1_LOAD

    const int off = g_off[e];
#pragma unroll
    for (int mf = 0; mf < 2; mf++)
#pragma unroll
    for (int nf = 0; nf < 4; nf++) {
        int col = nt*64 + wn*32 + nf*8 + (lane & 3)*2;
#pragma unroll
        for (int half = 0; half < 2; half++) {
            int row = mt*128 + wm*32 + mf*16 + (lane >> 2) + half*8;
            if (row < cnt) {
                float g0 = cg[mf][nf][half*2],   g1 = cg[mf][nf][half*2+1];
                float u0 = cu[mf][nf][half*2],   u1 = cu[mf][nf][half*2+1];
                float h0 = (g0 / (1.f + expf(-g0))) * u0;
                float h1 = (g1 / (1.f + expf(-g1))) * u1;
                size_t base = (size_t)(off + row) * I_DIM + col;
                *(uint32_t*)(g_h + base) = packh2(__float2half_rn(h0), __float2half_rn(h1));
            }
        }
    }
}

// ---------------------------------------------------------------------------
// gemm2: y = He @ Wd^T, fused combine: atomicAdd(out[tok], w * y).
__global__ __launch_bounds__(256, 2) void gemm2_kernel(float* __restrict__ out)
{
    const int e  = blockIdx.z;
    const int mt = blockIdx.y;
    const int nt = blockIdx.x;
    const int cnt = g_cnt[e];
    if (mt * 128 >= cnt) return;
    const int tid = threadIdx.x;
    const int wid = tid >> 5;
    const int lane = tid & 31;
    const int off = g_off[e];

    extern __shared__ __half sm[];
    __shared__ int   stok2[128];
    __shared__ float swt[128];

    if (tid < 128) {
        int row = mt * 128 + tid;
        if (row < cnt) {
            stok2[tid] = g_tok[e * MAXTOK + row];
            swt[tid]   = g_wt [e * MAXTOK + row];
        } else { stok2[tid] = 0; swt[tid] = 0.f; }
    }

    const size_t wbase = (size_t)e * H_DIM * I_DIM + (size_t)(nt * 64) * I_DIM;
    const __half* wdp = g_wd + wbase;

    const uint32_t smb = smem_u32(sm);

    const __half* aSrc[4]; uint32_t aDst[4];
#pragma unroll
    for (int p = 0; p < 4; p++) {
        int q = tid + p * 256;
        int r = q >> 3, c8 = (q & 7) * 8;
        aSrc[p] = g_h + (size_t)(off + mt*128 + r) * I_DIM + c8;
        aDst[p] = smb + (uint32_t)(r * AS + c8) * 2u;
    }
    size_t bOfs[2]; uint32_t bDst[2];
#pragma unroll
    for (int p = 0; p < 2; p++) {
        int q = tid + p * 256;
        int n = q >> 3, c8 = (q & 7) * 8;
        bOfs[p] = (size_t)n * I_DIM + c8;
        bDst[p] = smb + (uint32_t)(n * AS + c8) * 2u;
    }

#define G2_LOAD(S, KK) do {                                                     \
    uint32_t so = (uint32_t)(S) * G2_STG_B;                                     \
    _Pragma("unroll")                                                           \
    for (int p = 0; p < 4; p++)                                                 \
        cp16(aDst[p] + so, aSrc[p] + (KK), 16u);                                \
    _Pragma("unroll")                                                           \
    for (int p = 0; p < 2; p++)                                                 \
        cp16(bDst[p] + so + 128*AS*2, wdp + bOfs[p] + (KK), 16u);               \
} while (0)

    float cc[2][4][4];
#pragma unroll
    for (int i = 0; i < 2; i++)
#pragma unroll
        for (int j = 0; j < 4; j++)
#pragma unroll
            for (int k = 0; k < 4; k++) cc[i][j][k] = 0.f;

    const int wm = wid >> 1;
    const int wn = wid & 1;
    const int lr = lane & 15;
    const int lc = (lane >> 4) * 8;

    const uint32_t aB  = smb + (uint32_t)(((wm*32 + lr) * AS + lc) * 2);
    const uint32_t bdB = smb + (uint32_t)((128*AS + (wn*32 + lr) * AS + lc) * 2);

    G2_LOAD(0, 0);
    CP_COMMIT();
    G2_LOAD(1, 64);
    CP_COMMIT();

    const int KT = I_DIM / 64;
    int cur = 0, nxt = 2;
#pragma unroll 3
    for (int kt = 0; kt < KT; kt++) {
        if (kt + 1 < KT) cp_wait<1>(); else cp_wait<0>();
        __syncthreads();
        if (kt + 2 < KT) {
            G2_LOAD(nxt, (kt + 2) * 64);
            CP_COMMIT();
        }

        const uint32_t so = (uint32_t)cur * G2_STG_B;

#pragma unroll
        for (int ks = 0; ks < 4; ks++) {
            uint32_t ah[2][4];
#pragma unroll
            for (int mf = 0; mf < 2; mf++)
                ldsm_x4(ah[mf], aB + so + (uint32_t)((mf*16*AS + ks*16) * 2));
            uint32_t bd[2][4];
#pragma unroll
            for (int n2 = 0; n2 < 2; n2++)
                ldsm_x4(bd[n2], bdB + so + (uint32_t)((n2*16*AS + ks*16) * 2));
#pragma unroll
            for (int mf = 0; mf < 2; mf++)
#pragma unroll
            for (int nf = 0; nf < 4; nf++) {
                int n2 = nf >> 1, nh = nf & 1;
                uint32_t bB[2] = { bd[n2][nh], bd[n2][nh+2] };
                mma_fp16(cc[mf][nf], ah[mf], bB);
            }
        }
        cur = (cur == 2) ? 0 : cur + 1;
        nxt = (nxt == 2) ? 0 : nxt + 1;
    }
#undef G2_LOAD

    // fused combine epilogue: out[tok] += w * y (exact-commutative fp32 adds)
#pragma unroll
    for (int mf = 0; mf < 2; mf++)
#pragma unroll
    for (int nf = 0; nf < 4; nf++) {
        int col = nt*64 + wn*32 + nf*8 + (lane & 3)*2;
#pragma unroll
        for (int half = 0; half < 2; half++) {
            int mloc = wm*32 + mf*16 + (lane >> 2) + half*8;
            int row = mt*128 + mloc;
            if (row < cnt) {
                int tok = stok2[mloc];
                float w = swt[mloc];
                float* o = out + (size_t)tok * H_DIM + col;
                atomicAdd(o,     w * cc[mf][nf][half*2]);
                atomicAdd(o + 1, w * cc[mf][nf][half*2+1]);
            }
        }
    }
}

// ---------------------------------------------------------------------------
extern "C" void kernel_launch(void* const* d_in, const int* in_sizes, int n_in,
                              void* d_out, int out_size)
{
    const float* hs   = (const float*)d_in[0];
    const float* rmsw = (const float*)d_in[1];
    const float* rw   = (const float*)d_in[2];
    const float* wg   = (const float*)d_in[3];
    const float* wu   = (const float*)d_in[4];
    const float* wd   = (const float*)d_in[5];

    float* out        = (float*)d_out;
    float* out_logits = (float*)d_out + (size_t)T_TOKENS * H_DIM;

    cudaFuncSetAttribute(prep_kernel,  cudaFuncAttributeMaxDynamicSharedMemorySize, PREP_SMEM);
    cudaFuncSetAttribute(gemm1_kernel, cudaFuncAttributeMaxDynamicSharedMemorySize, G1_SMEM);
    cudaFuncSetAttribute(gemm2_kernel, cudaFuncAttributeMaxDynamicSharedMemorySize, G2_SMEM);

    reset_kernel<<<1, 32>>>();

    int grid = RBLOCKS + 3 * SPLIT_BLK;
    prep_kernel<<<grid, 256, PREP_SMEM>>>(hs, rmsw, rw, wg, wu, wd, out, out_logits);

    offsets_kernel<<<1, 1>>>();

    dim3 g1(I_DIM / 64, T_TOKENS / 128, N_EXP);   // 22 x 64 x 8
    gemm1_kernel<<<g1, 256, G1_SMEM>>>();

    dim3 g2(H_DIM / 64, T_TOKENS / 128, N_EXP);   // 32 x 64 x 8
    gemm2_kernel<<<g2, 256, G2_SMEM>>>(out);
}

// round 15
// speedup vs baseline: 1.0126x; 1.0126x over previous
#include <cuda_runtime.h>
#include <cuda_fp16.h>
#include <math.h>
#include <stdint.h>

#define T_TOKENS 8192
#define H_DIM    2048
#define I_DIM    1408
#define N_EXP    8
#define MAXTOK   8192
#define TOTROWS  (2*T_TOKENS)
#define WELEMS   (N_EXP * I_DIM * H_DIM)
#define SPLIT_N4 (WELEMS / 4)
#define SPLIT_IT 4
#define SPLIT_BLK ((SPLIT_N4 + 256*SPLIT_IT - 1) / (256*SPLIT_IT))

// ---------------- scratch (static device globals) ----------------
__device__ __half g_xn[(size_t)T_TOKENS*H_DIM];
__device__ __half g_h [(size_t)(TOTROWS+128)*I_DIM];
__device__ int    g_cnt[N_EXP];
__device__ int    g_tok[N_EXP*MAXTOK];
__device__ float  g_wt [N_EXP*MAXTOK];
// fp16 weights (single term)
__device__ __half g_wg[(size_t)WELEMS];
__device__ __half g_wu[(size_t)WELEMS];
__device__ __half g_wd[(size_t)WELEMS];

// ---------------- helpers ----------------
__device__ __forceinline__ uint32_t smem_u32(const void* p) {
    uint32_t a;
    asm("{ .reg .u64 t; cvta.to.shared.u64 t, %1; cvt.u32.u64 %0, t; }" : "=r"(a) : "l"(p));
    return a;
}
__device__ __forceinline__ void ldsm_x4(uint32_t* r, uint32_t addr) {
    asm volatile("ldmatrix.sync.aligned.m8n8.x4.shared.b16 {%0,%1,%2,%3}, [%4];"
        : "=r"(r[0]), "=r"(r[1]), "=r"(r[2]), "=r"(r[3]) : "r"(addr));
}
__device__ __forceinline__ void mma_fp16(float* c, const uint32_t* a, const uint32_t* b) {
    asm volatile(
        "mma.sync.aligned.m16n8k16.row.col.f32.f16.f16.f32 "
        "{%0,%1,%2,%3}, {%4,%5,%6,%7}, {%8,%9}, {%0,%1,%2,%3};"
        : "+f"(c[0]), "+f"(c[1]), "+f"(c[2]), "+f"(c[3])
        : "r"(a[0]), "r"(a[1]), "r"(a[2]), "r"(a[3]), "r"(b[0]), "r"(b[1]));
}
__device__ __forceinline__ void cp16(uint32_t dst, const void* src, uint32_t sz) {
    asm volatile("cp.async.cg.shared.global [%0], [%1], 16, %2;"
        :: "r"(dst), "l"(src), "r"(sz) : "memory");
}
#define CP_COMMIT() asm volatile("cp.async.commit_group;" ::: "memory")
template<int N> __device__ __forceinline__ void cp_wait() {
    asm volatile("cp.async.wait_group %0;" :: "n"(N) : "memory");
}
__device__ __forceinline__ uint32_t packh2(__half a, __half b) {
    __half2 v = __halves2half2(a, b);
    return *reinterpret_cast<uint32_t*>(&v);
}
__device__ __forceinline__ float warp_sum(float v) {
#pragma unroll
    for (int o = 16; o > 0; o >>= 1)
        v += __shfl_xor_sync(0xFFFFFFFFu, v, o);
    return v;
}

// ---------------------------------------------------------------------------
__global__ void reset_kernel() {
    if (threadIdx.x < N_EXP) g_cnt[threadIdx.x] = 0;
}

// ---------------------------------------------------------------------------
// weight cast fp32 -> fp16 (runs on stream 2, overlapped with router)
__global__ __launch_bounds__(256) void cast_kernel(
    const float* __restrict__ wg,
    const float* __restrict__ wu,
    const float* __restrict__ wd)
{
    int sb = blockIdx.x;
    int w = sb / SPLIT_BLK;
    const float* src = (w == 0) ? wg : (w == 1) ? wu : wd;
    __half* hi = (w == 0) ? g_wg : (w == 1) ? g_wu : g_wd;
    int base = (sb - w * SPLIT_BLK) * 256 * SPLIT_IT + threadIdx.x;
#pragma unroll
    for (int it = 0; it < SPLIT_IT; it++, base += 256) {
        if (base < SPLIT_N4) {
            float4 v = ((const float4*)src)[base];
            ((uint2*)hi)[base] = make_uint2(
                packh2(__float2half_rn(v.x), __float2half_rn(v.y)),
                packh2(__float2half_rn(v.z), __float2half_rn(v.w)));
        }
    }
}

// ---------------------------------------------------------------------------
// Router: RMSNorm + logits + top-2 + zero out rows (round-13 form).
__global__ __launch_bounds__(256) void router_kernel(
    const float* __restrict__ hs,
    const float* __restrict__ rmsw,
    const float* __restrict__ rw,
    float* __restrict__ out,
    float* __restrict__ out_logits)
{
    const int tid = threadIdx.x;
    const int t    = blockIdx.x;
    const int wid  = tid >> 5;
    const int lane = tid & 31;
    const float* x = hs + (size_t)t * H_DIM;

    // zero this token's output row (gemm2 accumulates atomically)
    {
        float4 z = make_float4(0.f, 0.f, 0.f, 0.f);
        float* orow = out + (size_t)t * H_DIM;
#pragma unroll
        for (int it = 0; it < 2; it++)
            *(float4*)(orow + (tid + it * 256) * 4) = z;
    }

    __shared__ float swred[8];
    __shared__ float sacc[8][N_EXP];
    __shared__ float s_scale;
    __shared__ float slog[N_EXP];

    float ss = 0.f;
    for (int i = tid; i < H_DIM; i += 256) { float v = x[i]; ss += v * v; }
    ss = warp_sum(ss);
    if (lane == 0) swred[wid] = ss;
    __syncthreads();
    if (tid == 0) {
        float tot = 0.f;
#pragma unroll
        for (int w = 0; w < 8; w++) tot += swred[w];
        s_scale = rsqrtf(tot / (float)H_DIM + 1e-6f);
    }
    __syncthreads();
    const float scale = s_scale;

    float acc[N_EXP];
#pragma unroll
    for (int e = 0; e < N_EXP; e++) acc[e] = 0.f;
    for (int i = tid; i < H_DIM; i += 256) {
        float v = x[i] * scale * rmsw[i];
        g_xn[(size_t)t * H_DIM + i] = __float2half_rn(v);
#pragma unroll
        for (int e = 0; e < N_EXP; e++) acc[e] += v * rw[e * H_DIM + i];
    }
#pragma unroll
    for (int e = 0; e < N_EXP; e++) {
        float v = warp_sum(acc[e]);
        if (lane == 0) sacc[wid][e] = v;
    }
    __syncthreads();
    if (tid < N_EXP) {
        float tot = 0.f;
#pragma unroll
        for (int w = 0; w < 8; w++) tot += sacc[w][tid];
        slog[tid] = tot;
    }
    __syncthreads();

    if (tid == 0) {
        float l[N_EXP], m = -1e30f;
#pragma unroll
        for (int e = 0; e < N_EXP; e++) {
            l[e] = slog[e];
            out_logits[(size_t)t * N_EXP + e] = l[e];
            m = fmaxf(m, l[e]);
        }
        float p[N_EXP], s = 0.f;
#pragma unroll
        for (int e = 0; e < N_EXP; e++) { p[e] = expf(l[e] - m); s += p[e]; }
#pragma unroll
        for (int e = 0; e < N_EXP; e++) p[e] /= s;

        int a = 0;
#pragma unroll
        for (int e = 1; e < N_EXP; e++) if (p[e] > p[a]) a = e;
        int b = (a == 0) ? 1 : 0;
#pragma unroll
        for (int e = 0; e < N_EXP; e++) if (e != a && p[e] > p[b]) b = e;

        float wsum = p[a] + p[b] + 1e-20f;
        float wa = p[a] / wsum, wb = p[b] / wsum;

        int pa = atomicAdd(&g_cnt[a], 1);
        g_tok[a * MAXTOK + pa] = t;  g_wt[a * MAXTOK + pa] = wa;
        int pb = atomicAdd(&g_cnt[b], 1);
        g_tok[b * MAXTOK + pb] = t;  g_wt[b * MAXTOK + pb] = wb;
    }
}

// ---------------------------------------------------------------------------
// fp16 HMMA GEMMs, 3-stage cp.async pipeline, one sync per K-tile.
// Block tile 128(M) x 64(N), K-tile 64, 256 threads, warp grid 4x2 (warp 32x32),
// 2 CTAs/SM. Expert offsets computed inline (offsets_kernel removed).
#define AS 72
#define G1_STG_E (256*AS)                  // halves per stage = 18432
#define G1_STG_B (G1_STG_E*2)              // 36864 B
#define G1_SMEM  (3*G1_STG_B)              // 110592 B
#define G2_STG_E (192*AS)                  // 13824
#define G2_STG_B (G2_STG_E*2)              // 27648 B
#define G2_SMEM  (3*G2_STG_B)              // 82944 B

__global__ __launch_bounds__(256, 2) void gemm1_kernel()
{
    const int e  = blockIdx.z;
    const int mt = blockIdx.y;
    const int nt = blockIdx.x;
    const int cnt = g_cnt[e];
    if (mt * 128 >= cnt) return;
    const int tid = threadIdx.x;
    const int wid = tid >> 5;
    const int lane = tid & 31;

    // inline expert offset (prefix sum of g_cnt)
    int off = 0;
    for (int i = 0; i < e; i++) off += g_cnt[i];

    extern __shared__ __half sm[];
    __shared__ int stok[128];

    if (tid < 128) {
        int row = mt * 128 + tid;
        stok[tid] = (row < cnt) ? g_tok[e * MAXTOK + row] : -1;
    }
    __syncthreads();

    const size_t wbase = (size_t)e * I_DIM * H_DIM + (size_t)(nt * 64) * H_DIM;
    const __half* wgp = g_wg + wbase;
    const __half* wup = g_wu + wbase;

    const uint32_t smb = smem_u32(sm);

    const __half* aSrc[4]; uint32_t aDst[4], aSz[4];
#pragma unroll
    for (int p = 0; p < 4; p++) {
        int q = tid + p * 256;
        int r = q >> 3, c8 = (q & 7) * 8;
        int tok = stok[r];
        aSz[p]  = tok >= 0 ? 16u : 0u;
        aSrc[p] = g_xn + (size_t)(tok < 0 ? 0 : tok) * H_DIM + c8;
        aDst[p] = smb + (uint32_t)(r * AS + c8) * 2u;
    }
    size_t bOfs[2]; uint32_t bDst[2];
#pragma unroll
    for (int p = 0; p < 2; p++) {
        int q = tid + p * 256;
        int n = q >> 3, c8 = (q & 7) * 8;
        bOfs[p] = (size_t)n * H_DIM + c8;
        bDst[p] = smb + (uint32_t)(n * AS + c8) * 2u;
    }

#define G1_LOAD(S, KK) do {                                                     \
    uint32_t so = (uint32_t)(S) * G1_STG_B;                                     \
    _Pragma("unroll")                                                           \
    for (int p = 0; p < 4; p++)                                                 \
        cp16(aDst[p] + so, aSrc[p] + (KK), aSz[p]);                             \
    _Pragma("unroll")                                                           \
    for (int p = 0; p < 2; p++) {                                               \
        size_t o = bOfs[p] + (KK);                                              \
        cp16(bDst[p] + so + 128*AS*2, wgp + o, 16u);                            \
        cp16(bDst[p] + so + 192*AS*2, wup + o, 16u);                            \
    }                                                                           \
} while (0)

    float cg[2][4][4], cu[2][4][4];
#pragma unroll
    for (int i = 0; i < 2; i++)
#pragma unroll
        for (int j = 0; j < 4; j++)
#pragma unroll
            for (int k = 0; k < 4; k++) { cg[i][j][k] = 0.f; cu[i][j][k] = 0.f; }

    const int wm = wid >> 1;
    const int wn = wid & 1;
    const int lr = lane & 15;
    const int lc = (lane >> 4) * 8;

    const uint32_t aB  = smb + (uint32_t)(((wm*32 + lr) * AS + lc) * 2);
    const uint32_t bgB = smb + (uint32_t)((128*AS + (wn*32 + lr) * AS + lc) * 2);
    const uint32_t buB = bgB + 64*AS*2;

    G1_LOAD(0, 0);
    CP_COMMIT();
    G1_LOAD(1, 64);
    CP_COMMIT();

    const int KT = H_DIM / 64;
    int cur = 0, nxt = 2;
#pragma unroll 3
    for (int kt = 0; kt < KT; kt++) {
        if (kt + 1 < KT) cp_wait<1>(); else cp_wait<0>();
        __syncthreads();
        if (kt + 2 < KT) {
            G1_LOAD(nxt, (kt + 2) * 64);
            CP_COMMIT();
        }

        const uint32_t so = (uint32_t)cur * G1_STG_B;

#pragma unroll
        for (int ks = 0; ks < 4; ks++) {
            uint32_t ah[2][4];
#pragma unroll
            for (int mf = 0; mf < 2; mf++)
                ldsm_x4(ah[mf], aB + so + (uint32_t)((mf*16*AS + ks*16) * 2));
            uint32_t bg[2][4], bu[2][4];
#pragma unroll
            for (int n2 = 0; n2 < 2; n2++) {
                uint32_t fo = (uint32_t)((n2*16*AS + ks*16) * 2);
                ldsm_x4(bg[n2], bgB + so + fo);
                ldsm_x4(bu[n2], buB + so + fo);
            }
#pragma unroll
            for (int mf = 0; mf < 2; mf++)
#pragma unroll
            for (int nf = 0; nf < 4; nf++) {
                int n2 = nf >> 1, nh = nf & 1;
                uint32_t bG[2] = { bg[n2][nh], bg[n2][nh+2] };
                uint32_t bU[2] = { bu[n2][nh], bu[n2][nh+2] };
                mma_fp16(cg[mf][nf], ah[mf], bG);
                mma_fp16(cu[mf][nf], ah[mf], bU);
            }
        }
        cur = (cur == 2) ? 0 : cur + 1;
        nxt = (nxt == 2) ? 0 : nxt + 1;
    }
#undef G1_LOAD

#pragma unroll
    for (int mf = 0; mf < 2; mf++)
#pragma unroll
    for (int nf = 0; nf < 4; nf++) {
        int col = nt*64 + wn*32 + nf*8 + (lane & 3)*2;
#pragma unroll
        for (int half = 0; half < 2; half++) {
            int row = mt*128 + wm*32 + mf*16 + (lane >> 2) + half*8;
            if (row < cnt) {
                float g0 = cg[mf][nf][half*2],   g1 = cg[mf][nf][half*2+1];
                float u0 = cu[mf][nf][half*2],   u1 = cu[mf][nf][half*2+1];
                float h0 = (g0 / (1.f + expf(-g0))) * u0;
                float h1 = (g1 / (1.f + expf(-g1))) * u1;
                size_t base = (size_t)(off + row) * I_DIM + col;
                *(uint32_t*)(g_h + base) = packh2(__float2half_rn(h0), __float2half_rn(h1));
            }
        }
    }
}

// ---------------------------------------------------------------------------
// gemm2: y = He @ Wd^T, fused combine: atomicAdd(out[tok], w * y).
__global__ __launch_bounds__(256, 2) void gemm2_kernel(float* __restrict__ out)
{
    const int e  = blockIdx.z;
    const int mt = blockIdx.y;
    const int nt = blockIdx.x;
    const int cnt = g_cnt[e];
    if (mt * 128 >= cnt) return;
    const int tid = threadIdx.x;
    const int wid = tid >> 5;
    const int lane = tid & 31;

    int off = 0;
    for (int i = 0; i < e; i++) off += g_cnt[i];

    extern __shared__ __half sm[];
    __shared__ int   stok2[128];
    __shared__ float swt[128];

    if (tid < 128) {
        int row = mt * 128 + tid;
        if (row < cnt) {
            stok2[tid] = g_tok[e * MAXTOK + row];
            swt[tid]   = g_wt [e * MAXTOK + row];
        } else { stok2[tid] = 0; swt[tid] = 0.f; }
    }

    const size_t wbase = (size_t)e * H_DIM * I_DIM + (size_t)(nt * 64) * I_DIM;
    const __half* wdp = g_wd + wbase;

    const uint32_t smb = smem_u32(sm);

    const __half* aSrc[4]; uint32_t aDst[4];
#pragma unroll
    for (int p = 0; p < 4; p++) {
        int q = tid + p * 256;
        int r = q >> 3, c8 = (q & 7) * 8;
        aSrc[p] = g_h + (size_t)(off + mt*128 + r) * I_DIM + c8;
        aDst[p] = smb + (uint32_t)(r * AS + c8) * 2u;
    }
    size_t bOfs[2]; uint32_t bDst[2];
#pragma unroll
    for (int p = 0; p < 2; p++) {
        int q = tid + p * 256;
        int n = q >> 3, c8 = (q & 7) * 8;
        bOfs[p] = (size_t)n * I_DIM + c8;
        bDst[p] = smb + (uint32_t)(n * AS + c8) * 2u;
    }

#define G2_LOAD(S, KK) do {                                                     \
    uint32_t so = (uint32_t)(S) * G2_STG_B;                                     \
    _Pragma("unroll")                                                           \
    for (int p = 0; p < 4; p++)                                                 \
        cp16(aDst[p] + so, aSrc[p] + (KK), 16u);                                \
    _Pragma("unroll")                                                           \
    for (int p = 0; p < 2; p++)                                                 \
        cp16(bDst[p] + so + 128*AS*2, wdp + bOfs[p] + (KK), 16u);               \
} while (0)

    float cc[2][4][4];
#pragma unroll
    for (int i = 0; i < 2; i++)
#pragma unroll
        for (int j = 0; j < 4; j++)
#pragma unroll
            for (int k = 0; k < 4; k++) cc[i][j][k] = 0.f;

    const int wm = wid >> 1;
    const int wn = wid & 1;
    const int lr = lane & 15;
    const int lc = (lane >> 4) * 8;

    const uint32_t aB  = smb + (uint32_t)(((wm*32 + lr) * AS + lc) * 2);
    const uint32_t bdB = smb + (uint32_t)((128*AS + (wn*32 + lr) * AS + lc) * 2);

    G2_LOAD(0, 0);
    CP_COMMIT();
    G2_LOAD(1, 64);
    CP_COMMIT();

    const int KT = I_DIM / 64;
    int cur = 0, nxt = 2;
#pragma unroll 3
    for (int kt = 0; kt < KT; kt++) {
        if (kt + 1 < KT) cp_wait<1>(); else cp_wait<0>();
        __syncthreads();
        if (kt + 2 < KT) {
            G2_LOAD(nxt, (kt + 2) * 64);
            CP_COMMIT();
        }

        const uint32_t so = (uint32_t)cur * G2_STG_B;

#pragma unroll
        for (int ks = 0; ks < 4; ks++) {
            uint32_t ah[2][4];
#pragma unroll
            for (int mf = 0; mf < 2; mf++)
                ldsm_x4(ah[mf], aB + so + (uint32_t)((mf*16*AS + ks*16) * 2));
            uint32_t bd[2][4];
#pragma unroll
            for (int n2 = 0; n2 < 2; n2++)
                ldsm_x4(bd[n2], bdB + so + (uint32_t)((n2*16*AS + ks*16) * 2));
#pragma unroll
            for (int mf = 0; mf < 2; mf++)
#pragma unroll
            for (int nf = 0; nf < 4; nf++) {
                int n2 = nf >> 1, nh = nf & 1;
                uint32_t bB[2] = { bd[n2][nh], bd[n2][nh+2] };
                mma_fp16(cc[mf][nf], ah[mf], bB);
            }
        }
        cur = (cur == 2) ? 0 : cur + 1;
        nxt = (nxt == 2) ? 0 : nxt + 1;
    }
#undef G2_LOAD

    // fused combine epilogue: out[tok] += w * y (exact-commutative fp32 adds)
#pragma unroll
    for (int mf = 0; mf < 2; mf++)
#pragma unroll
    for (int nf = 0; nf < 4; nf++) {
        int col = nt*64 + wn*32 + nf*8 + (lane & 3)*2;
#pragma unroll
        for (int half = 0; half < 2; half++) {
            int mloc = wm*32 + mf*16 + (lane >> 2) + half*8;
            int row = mt*128 + mloc;
            if (row < cnt) {
                int tok = stok2[mloc];
                float w = swt[mloc];
                float* o = out + (size_t)tok * H_DIM + col;
                atomicAdd(o,     w * cc[mf][nf][half*2]);
                atomicAdd(o + 1, w * cc[mf][nf][half*2+1]);
            }
        }
    }
}

// ---------------------------------------------------------------------------
extern "C" void kernel_launch(void* const* d_in, const int* in_sizes, int n_in,
                              void* d_out, int out_size)
{
    const float* hs   = (const float*)d_in[0];
    const float* rmsw = (const float*)d_in[1];
    const float* rw   = (const float*)d_in[2];
    const float* wg   = (const float*)d_in[3];
    const float* wu   = (const float*)d_in[4];
    const float* wd   = (const float*)d_in[5];

    float* out        = (float*)d_out;
    float* out_logits = (float*)d_out + (size_t)T_TOKENS * H_DIM;

    // one-time side stream + events (created on first call, outside capture;
    // identical work is enqueued on every call)
    struct Aux {
        cudaStream_t s2;
        cudaEvent_t fork, cast_done;
        Aux() {
            cudaStreamCreateWithFlags(&s2, cudaStreamNonBlocking);
            cudaEventCreateWithFlags(&fork, cudaEventDisableTiming);
            cudaEventCreateWithFlags(&cast_done, cudaEventDisableTiming);
        }
    };
    static Aux aux;

    cudaFuncSetAttribute(gemm1_kernel, cudaFuncAttributeMaxDynamicSharedMemorySize, G1_SMEM);
    cudaFuncSetAttribute(gemm2_kernel, cudaFuncAttributeMaxDynamicSharedMemorySize, G2_SMEM);

    // fork: weight cast on stream 2, overlapped with router on main stream
    cudaEventRecord(aux.fork, 0);
    cudaStreamWaitEvent(aux.s2, aux.fork, 0);
    cast_kernel<<<3 * SPLIT_BLK, 256, 0, aux.s2>>>(wg, wu, wd);
    cudaEventRecord(aux.cast_done, aux.s2);

    reset_kernel<<<1, 32>>>();
    router_kernel<<<T_TOKENS, 256>>>(hs, rmsw, rw, out, out_logits);

    // join: gemm1 needs both router outputs and cast weights
    cudaStreamWaitEvent(0, aux.cast_done, 0);

    dim3 g1(I_DIM / 64, T_TOKENS / 128, N_EXP);   // 22 x 64 x 8
    gemm1_kernel<<<g1, 256, G1_SMEM>>>();

    dim3 g2(H_DIM / 64, T_TOKENS / 128, N_EXP);   // 32 x 64 x 8
    gemm2_kernel<<<g2, 256, G2_SMEM>>>(out);
}

// round 16
// speedup vs baseline: 1.0708x; 1.0576x over previous
#include <cuda_runtime.h>
#include <cuda_fp16.h>
#include <math.h>
#include <stdint.h>

#define T_TOKENS 8192
#define H_DIM    2048
#define I_DIM    1408
#define N_EXP    8
#define MAXTOK   8192
#define TOTROWS  (2*T_TOKENS)
#define WELEMS   (N_EXP * I_DIM * H_DIM)
#define SPLIT_N4 (WELEMS / 4)
#define SPLIT_IT 4
#define SPLIT_BLK ((SPLIT_N4 + 256*SPLIT_IT - 1) / (256*SPLIT_IT))

// ---------------- scratch (static device globals) ----------------
__device__ __half g_xn[(size_t)T_TOKENS*H_DIM];
__device__ __half g_h [(size_t)(TOTROWS+128)*I_DIM];
__device__ int    g_cnt[N_EXP];
__device__ int    g_tok[N_EXP*MAXTOK];
__device__ float  g_wt [N_EXP*MAXTOK];
// fp16 weights (single term)
__device__ __half g_wg[(size_t)WELEMS];
__device__ __half g_wu[(size_t)WELEMS];
__device__ __half g_wd[(size_t)WELEMS];

// ---------------- helpers ----------------
__device__ __forceinline__ uint32_t smem_u32(const void* p) {
    uint32_t a;
    asm("{ .reg .u64 t; cvta.to.shared.u64 t, %1; cvt.u32.u64 %0, t; }" : "=r"(a) : "l"(p));
    return a;
}
__device__ __forceinline__ void ldsm_x4(uint32_t* r, uint32_t addr) {
    asm volatile("ldmatrix.sync.aligned.m8n8.x4.shared.b16 {%0,%1,%2,%3}, [%4];"
        : "=r"(r[0]), "=r"(r[1]), "=r"(r[2]), "=r"(r[3]) : "r"(addr));
}
__device__ __forceinline__ void mma_fp16(float* c, const uint32_t* a, const uint32_t* b) {
    asm volatile(
        "mma.sync.aligned.m16n8k16.row.col.f32.f16.f16.f32 "
        "{%0,%1,%2,%3}, {%4,%5,%6,%7}, {%8,%9}, {%0,%1,%2,%3};"
        : "+f"(c[0]), "+f"(c[1]), "+f"(c[2]), "+f"(c[3])
        : "r"(a[0]), "r"(a[1]), "r"(a[2]), "r"(a[3]), "r"(b[0]), "r"(b[1]));
}
__device__ __forceinline__ void cp16(uint32_t dst, const void* src, uint32_t sz) {
    asm volatile("cp.async.cg.shared.global [%0], [%1], 16, %2;"
        :: "r"(dst), "l"(src), "r"(sz) : "memory");
}
#define CP_COMMIT() asm volatile("cp.async.commit_group;" ::: "memory")
template<int N> __device__ __forceinline__ void cp_wait() {
    asm volatile("cp.async.wait_group %0;" :: "n"(N) : "memory");
}
__device__ __forceinline__ uint32_t packh2(__half a, __half b) {
    __half2 v = __halves2half2(a, b);
    return *reinterpret_cast<uint32_t*>(&v);
}
__device__ __forceinline__ float warp_sum(float v) {
#pragma unroll
    for (int o = 16; o > 0; o >>= 1)
        v += __shfl_xor_sync(0xFFFFFFFFu, v, o);
    return v;
}

// ---------------------------------------------------------------------------
__global__ void reset_kernel() {
    if (threadIdx.x < N_EXP) g_cnt[threadIdx.x] = 0;
}

// ---------------------------------------------------------------------------
// weight cast fp32 -> fp16 (runs on stream 2, overlapped with router)
__global__ __launch_bounds__(256) void cast_kernel(
    const float* __restrict__ wg,
    const float* __restrict__ wu,
    const float* __restrict__ wd)
{
    int sb = blockIdx.x;
    int w = sb / SPLIT_BLK;
    const float* src = (w == 0) ? wg : (w == 1) ? wu : wd;
    __half* hi = (w == 0) ? g_wg : (w == 1) ? g_wu : g_wd;
    int base = (sb - w * SPLIT_BLK) * 256 * SPLIT_IT + threadIdx.x;
#pragma unroll
    for (int it = 0; it < SPLIT_IT; it++, base += 256) {
        if (base < SPLIT_N4) {
            float4 v = ((const float4*)src)[base];
            ((uint2*)hi)[base] = make_uint2(
                packh2(__float2half_rn(v.x), __float2half_rn(v.y)),
                packh2(__float2half_rn(v.z), __float2half_rn(v.w)));
        }
    }
}

// ---------------------------------------------------------------------------
// Router: RMSNorm + logits + top-2 + zero out rows.
__global__ __launch_bounds__(256) void router_kernel(
    const float* __restrict__ hs,
    const float* __restrict__ rmsw,
    const float* __restrict__ rw,
    float* __restrict__ out,
    float* __restrict__ out_logits)
{
    const int tid = threadIdx.x;
    const int t    = blockIdx.x;
    const int wid  = tid >> 5;
    const int lane = tid & 31;
    const float* x = hs + (size_t)t * H_DIM;

    {
        float4 z = make_float4(0.f, 0.f, 0.f, 0.f);
        float* orow = out + (size_t)t * H_DIM;
#pragma unroll
        for (int it = 0; it < 2; it++)
            *(float4*)(orow + (tid + it * 256) * 4) = z;
    }

    __shared__ float swred[8];
    __shared__ float sacc[8][N_EXP];
    __shared__ float s_scale;
    __shared__ float slog[N_EXP];

    float ss = 0.f;
    for (int i = tid; i < H_DIM; i += 256) { float v = x[i]; ss += v * v; }
    ss = warp_sum(ss);
    if (lane == 0) swred[wid] = ss;
    __syncthreads();
    if (tid == 0) {
        float tot = 0.f;
#pragma unroll
        for (int w = 0; w < 8; w++) tot += swred[w];
        s_scale = rsqrtf(tot / (float)H_DIM + 1e-6f);
    }
    __syncthreads();
    const float scale = s_scale;

    float acc[N_EXP];
#pragma unroll
    for (int e = 0; e < N_EXP; e++) acc[e] = 0.f;
    for (int i = tid; i < H_DIM; i += 256) {
        float v = x[i] * scale * rmsw[i];
        g_xn[(size_t)t * H_DIM + i] = __float2half_rn(v);
#pragma unroll
        for (int e = 0; e < N_EXP; e++) acc[e] += v * rw[e * H_DIM + i];
    }
#pragma unroll
    for (int e = 0; e < N_EXP; e++) {
        float v = warp_sum(acc[e]);
        if (lane == 0) sacc[wid][e] = v;
    }
    __syncthreads();
    if (tid < N_EXP) {
        float tot = 0.f;
#pragma unroll
        for (int w = 0; w < 8; w++) tot += sacc[w][tid];
        slog[tid] = tot;
    }
    __syncthreads();

    if (tid == 0) {
        float l[N_EXP], m = -1e30f;
#pragma unroll
        for (int e = 0; e < N_EXP; e++) {
            l[e] = slog[e];
            out_logits[(size_t)t * N_EXP + e] = l[e];
            m = fmaxf(m, l[e]);
        }
        float p[N_EXP], s = 0.f;
#pragma unroll
        for (int e = 0; e < N_EXP; e++) { p[e] = expf(l[e] - m); s += p[e]; }
#pragma unroll
        for (int e = 0; e < N_EXP; e++) p[e] /= s;

        int a = 0;
#pragma unroll
        for (int e = 1; e < N_EXP; e++) if (p[e] > p[a]) a = e;
        int b = (a == 0) ? 1 : 0;
#pragma unroll
        for (int e = 0; e < N_EXP; e++) if (e != a && p[e] > p[b]) b = e;

        float wsum = p[a] + p[b] + 1e-20f;
        float wa = p[a] / wsum, wb = p[b] / wsum;

        int pa = atomicAdd(&g_cnt[a], 1);
        g_tok[a * MAXTOK + pa] = t;  g_wt[a * MAXTOK + pa] = wa;
        int pb = atomicAdd(&g_cnt[b], 1);
        g_tok[b * MAXTOK + pb] = t;  g_wt[b * MAXTOK + pb] = wb;
    }
}

// ---------------------------------------------------------------------------
// fp16 HMMA GEMMs, 3-stage cp.async pipeline, one sync per K-tile, 2 CTAs/SM.
// gemm1: 128(M) x 64(N), warp tile 32x32 (dual gate/up accumulators).
// gemm2: 128(M) x 128(N), warp tile 32x64 (single accumulator -> reg headroom).
#define AS 72
#define G1_STG_E (256*AS)                  // halves per stage = 18432
#define G1_STG_B (G1_STG_E*2)              // 36864 B
#define G1_SMEM  (3*G1_STG_B)              // 110592 B
#define G2_STG_E (256*AS)                  // A 128 + B 128 rows
#define G2_STG_B (G2_STG_E*2)              // 36864 B
#define G2_SMEM  (3*G2_STG_B)              // 110592 B

__global__ __launch_bounds__(256, 2) void gemm1_kernel()
{
    const int e  = blockIdx.z;
    const int mt = blockIdx.y;
    const int nt = blockIdx.x;
    const int cnt = g_cnt[e];
    if (mt * 128 >= cnt) return;
    const int tid = threadIdx.x;
    const int wid = tid >> 5;
    const int lane = tid & 31;

    int off = 0;
    for (int i = 0; i < e; i++) off += g_cnt[i];

    extern __shared__ __half sm[];
    __shared__ int stok[128];

    if (tid < 128) {
        int row = mt * 128 + tid;
        stok[tid] = (row < cnt) ? g_tok[e * MAXTOK + row] : -1;
    }
    __syncthreads();

    const size_t wbase = (size_t)e * I_DIM * H_DIM + (size_t)(nt * 64) * H_DIM;
    const __half* wgp = g_wg + wbase;
    const __half* wup = g_wu + wbase;

    const uint32_t smb = smem_u32(sm);

    const __half* aSrc[4]; uint32_t aDst[4], aSz[4];
#pragma unroll
    for (int p = 0; p < 4; p++) {
        int q = tid + p * 256;
        int r = q >> 3, c8 = (q & 7) * 8;
        int tok = stok[r];
        aSz[p]  = tok >= 0 ? 16u : 0u;
        aSrc[p] = g_xn + (size_t)(tok < 0 ? 0 : tok) * H_DIM + c8;
        aDst[p] = smb + (uint32_t)(r * AS + c8) * 2u;
    }
    size_t bOfs[2]; uint32_t bDst[2];
#pragma unroll
    for (int p = 0; p < 2; p++) {
        int q = tid + p * 256;
        int n = q >> 3, c8 = (q & 7) * 8;
        bOfs[p] = (size_t)n * H_DIM + c8;
        bDst[p] = smb + (uint32_t)(n * AS + c8) * 2u;
    }

#define G1_LOAD(S, KK) do {                                                     \
    uint32_t so = (uint32_t)(S) * G1_STG_B;                                     \
    _Pragma("unroll")                                                           \
    for (int p = 0; p < 4; p++)                                                 \
        cp16(aDst[p] + so, aSrc[p] + (KK), aSz[p]);                             \
    _Pragma("unroll")                                                           \
    for (int p = 0; p < 2; p++) {                                               \
        size_t o = bOfs[p] + (KK);                                              \
        cp16(bDst[p] + so + 128*AS*2, wgp + o, 16u);                            \
        cp16(bDst[p] + so + 192*AS*2, wup + o, 16u);                            \
    }                                                                           \
} while (0)

    float cg[2][4][4], cu[2][4][4];
#pragma unroll
    for (int i = 0; i < 2; i++)
#pragma unroll
        for (int j = 0; j < 4; j++)
#pragma unroll
            for (int k = 0; k < 4; k++) { cg[i][j][k] = 0.f; cu[i][j][k] = 0.f; }

    const int wm = wid >> 1;
    const int wn = wid & 1;
    const int lr = lane & 15;
    const int lc = (lane >> 4) * 8;

    const uint32_t aB  = smb + (uint32_t)(((wm*32 + lr) * AS + lc) * 2);
    const uint32_t bgB = smb + (uint32_t)((128*AS + (wn*32 + lr) * AS + lc) * 2);
    const uint32_t buB = bgB + 64*AS*2;

    G1_LOAD(0, 0);
    CP_COMMIT();
    G1_LOAD(1, 64);
    CP_COMMIT();

    const int KT = H_DIM / 64;
    int cur = 0, nxt = 2;
#pragma unroll 3
    for (int kt = 0; kt < KT; kt++) {
        if (kt + 1 < KT) cp_wait<1>(); else cp_wait<0>();
        __syncthreads();
        if (kt + 2 < KT) {
            G1_LOAD(nxt, (kt + 2) * 64);
            CP_COMMIT();
        }

        const uint32_t so = (uint32_t)cur * G1_STG_B;

#pragma unroll
        for (int ks = 0; ks < 4; ks++) {
            uint32_t ah[2][4];
#pragma unroll
            for (int mf = 0; mf < 2; mf++)
                ldsm_x4(ah[mf], aB + so + (uint32_t)((mf*16*AS + ks*16) * 2));
            uint32_t bg[2][4], bu[2][4];
#pragma unroll
            for (int n2 = 0; n2 < 2; n2++) {
                uint32_t fo = (uint32_t)((n2*16*AS + ks*16) * 2);
                ldsm_x4(bg[n2], bgB + so + fo);
                ldsm_x4(bu[n2], buB + so + fo);
            }
#pragma unroll
            for (int mf = 0; mf < 2; mf++)
#pragma unroll
            for (int nf = 0; nf < 4; nf++) {
                int n2 = nf >> 1, nh = nf & 1;
                uint32_t bG[2] = { bg[n2][nh], bg[n2][nh+2] };
                uint32_t bU[2] = { bu[n2][nh], bu[n2][nh+2] };
                mma_fp16(cg[mf][nf], ah[mf], bG);
                mma_fp16(cu[mf][nf], ah[mf], bU);
            }
        }
        cur = (cur == 2) ? 0 : cur + 1;
        nxt = (nxt == 2) ? 0 : nxt + 1;
    }
#undef G1_LOAD

#pragma unroll
    for (int mf = 0; mf < 2; mf++)
#pragma unroll
    for (int nf = 0; nf < 4; nf++) {
        int col = nt*64 + wn*32 + nf*8 + (lane & 3)*2;
#pragma unroll
        for (int half = 0; half < 2; half++) {
            int row = mt*128 + wm*32 + mf*16 + (lane >> 2) + half*8;
            if (row < cnt) {
                float g0 = cg[mf][nf][half*2],   g1 = cg[mf][nf][half*2+1];
                float u0 = cu[mf][nf][half*2],   u1 = cu[mf][nf][half*2+1];
                float h0 = (g0 / (1.f + expf(-g0))) * u0;
                float h1 = (g1 / (1.f + expf(-g1))) * u1;
                size_t base = (size_t)(off + row) * I_DIM + col;
                *(uint32_t*)(g_h + base) = packh2(__float2half_rn(h0), __float2half_rn(h1));
            }
        }
    }
}

// ---------------------------------------------------------------------------
// gemm2: y = He @ Wd^T, block 128x128, warp tile 32x64, fused atomic combine.
__global__ __launch_bounds__(256, 2) void gemm2_kernel(float* __restrict__ out)
{
    const int e  = blockIdx.z;
    const int mt = blockIdx.y;
    const int nt = blockIdx.x;
    const int cnt = g_cnt[e];
    if (mt * 128 >= cnt) return;
    const int tid = threadIdx.x;
    const int wid = tid >> 5;
    const int lane = tid & 31;

    int off = 0;
    for (int i = 0; i < e; i++) off += g_cnt[i];

    extern __shared__ __half sm[];
    __shared__ int   stok2[128];
    __shared__ float swt[128];

    if (tid < 128) {
        int row = mt * 128 + tid;
        if (row < cnt) {
            stok2[tid] = g_tok[e * MAXTOK + row];
            swt[tid]   = g_wt [e * MAXTOK + row];
        } else { stok2[tid] = 0; swt[tid] = 0.f; }
    }

    const size_t wbase = (size_t)e * H_DIM * I_DIM + (size_t)(nt * 128) * I_DIM;
    const __half* wdp = g_wd + wbase;

    const uint32_t smb = smem_u32(sm);

    const __half* aSrc[4]; uint32_t aDst[4];
#pragma unroll
    for (int p = 0; p < 4; p++) {
        int q = tid + p * 256;
        int r = q >> 3, c8 = (q & 7) * 8;
        aSrc[p] = g_h + (size_t)(off + mt*128 + r) * I_DIM + c8;
        aDst[p] = smb + (uint32_t)(r * AS + c8) * 2u;
    }
    size_t bOfs[4]; uint32_t bDst[4];
#pragma unroll
    for (int p = 0; p < 4; p++) {
        int q = tid + p * 256;
        int n = q >> 3, c8 = (q & 7) * 8;
        bOfs[p] = (size_t)n * I_DIM + c8;
        bDst[p] = smb + (uint32_t)((128*AS) + n * AS + c8) * 2u;
    }

#define G2_LOAD(S, KK) do {                                                     \
    uint32_t so = (uint32_t)(S) * G2_STG_B;                                     \
    _Pragma("unroll")                                                           \
    for (int p = 0; p < 4; p++)                                                 \
        cp16(aDst[p] + so, aSrc[p] + (KK), 16u);                                \
    _Pragma("unroll")                                                           \
    for (int p = 0; p < 4; p++)                                                 \
        cp16(bDst[p] + so, wdp + bOfs[p] + (KK), 16u);                          \
} while (0)

    float cc[2][8][4];
#pragma unroll
    for (int i = 0; i < 2; i++)
#pragma unroll
        for (int j = 0; j < 8; j++)
#pragma unroll
            for (int k = 0; k < 4; k++) cc[i][j][k] = 0.f;

    const int wm = wid >> 1;
    const int wn = wid & 1;
    const int lr = lane & 15;
    const int lc = (lane >> 4) * 8;

    const uint32_t aB  = smb + (uint32_t)(((wm*32 + lr) * AS + lc) * 2);
    const uint32_t bdB = smb + (uint32_t)((128*AS + (wn*64 + lr) * AS + lc) * 2);

    G2_LOAD(0, 0);
    CP_COMMIT();
    G2_LOAD(1, 64);
    CP_COMMIT();

    const int KT = I_DIM / 64;
    int cur = 0, nxt = 2;
#pragma unroll 3
    for (int kt = 0; kt < KT; kt++) {
        if (kt + 1 < KT) cp_wait<1>(); else cp_wait<0>();
        __syncthreads();
        if (kt + 2 < KT) {
            G2_LOAD(nxt, (kt + 2) * 64);
            CP_COMMIT();
        }

        const uint32_t so = (uint32_t)cur * G2_STG_B;

#pragma unroll
        for (int ks = 0; ks < 4; ks++) {
            uint32_t ah[2][4];
#pragma unroll
            for (int mf = 0; mf < 2; mf++)
                ldsm_x4(ah[mf], aB + so + (uint32_t)((mf*16*AS + ks*16) * 2));
            uint32_t bd[4][4];
#pragma unroll
            for (int n2 = 0; n2 < 4; n2++)
                ldsm_x4(bd[n2], bdB + so + (uint32_t)((n2*16*AS + ks*16) * 2));
#pragma unroll
            for (int mf = 0; mf < 2; mf++)
#pragma unroll
            for (int nf = 0; nf < 8; nf++) {
                int n2 = nf >> 1, nh = nf & 1;
                uint32_t bB[2] = { bd[n2][nh], bd[n2][nh+2] };
                mma_fp16(cc[mf][nf], ah[mf], bB);
            }
        }
        cur = (cur == 2) ? 0 : cur + 1;
        nxt = (nxt == 2) ? 0 : nxt + 1;
    }
#undef G2_LOAD

    // fused combine epilogue: out[tok] += w * y (exact-commutative fp32 adds)
#pragma unroll
    for (int mf = 0; mf < 2; mf++)
#pragma unroll
    for (int nf = 0; nf < 8; nf++) {
        int col = nt*128 + wn*64 + nf*8 + (lane & 3)*2;
#pragma unroll
        for (int half = 0; half < 2; half++) {
            int mloc = wm*32 + mf*16 + (lane >> 2) + half*8;
            int row = mt*128 + mloc;
            if (row < cnt) {
                int tok = stok2[mloc];
                float w = swt[mloc];
                float* o = out + (size_t)tok * H_DIM + col;
                atomicAdd(o,     w * cc[mf][nf][half*2]);
                atomicAdd(o + 1, w * cc[mf][nf][half*2+1]);
            }
        }
    }
}

// ---------------------------------------------------------------------------
extern "C" void kernel_launch(void* const* d_in, const int* in_sizes, int n_in,
                              void* d_out, int out_size)
{
    const float* hs   = (const float*)d_in[0];
    const float* rmsw = (const float*)d_in[1];
    const float* rw   = (const float*)d_in[2];
    const float* wg   = (const float*)d_in[3];
    const float* wu   = (const float*)d_in[4];
    const float* wd   = (const float*)d_in[5];

    float* out        = (float*)d_out;
    float* out_logits = (float*)d_out + (size_t)T_TOKENS * H_DIM;

    struct Aux {
        cudaStream_t s2;
        cudaEvent_t fork, cast_done;
        Aux() {
            cudaStreamCreateWithFlags(&s2, cudaStreamNonBlocking);
            cudaEventCreateWithFlags(&fork, cudaEventDisableTiming);
            cudaEventCreateWithFlags(&cast_done, cudaEventDisableTiming);
        }
    };
    static Aux aux;

    cudaFuncSetAttribute(gemm1_kernel, cudaFuncAttributeMaxDynamicSharedMemorySize, G1_SMEM);
    cudaFuncSetAttribute(gemm2_kernel, cudaFuncAttributeMaxDynamicSharedMemorySize, G2_SMEM);

    // fork: weight cast on stream 2, overlapped with router on main stream
    cudaEventRecord(aux.fork, 0);
    cudaStreamWaitEvent(aux.s2, aux.fork, 0);
    cast_kernel<<<3 * SPLIT_BLK, 256, 0, aux.s2>>>(wg, wu, wd);
    cudaEventRecord(aux.cast_done, aux.s2);

    reset_kernel<<<1, 32>>>();
    router_kernel<<<T_TOKENS, 256>>>(hs, rmsw, rw, out, out_logits);

    // join: gemm1 needs both router outputs and cast weights
    cudaStreamWaitEvent(0, aux.cast_done, 0);

    dim3 g1(I_DIM / 64, T_TOKENS / 128, N_EXP);    // 22 x 64 x 8
    gemm1_kernel<<<g1, 256, G1_SMEM>>>();

    dim3 g2(H_DIM / 128, T_TOKENS / 128, N_EXP);   // 16 x 64 x 8
    gemm2_kernel<<<g2, 256, G2_SMEM>>>(out);
}